// round 9
// baseline (speedup 1.0000x reference)
#include <cuda_runtime.h>
#include <cuda_bf16.h>
#include <cuda_fp16.h>
#include <cstdint>

#define NN 40000
#define EE 400000
#define GGR 64
#define IN_DIM 128
#define DD 64
#define HH 4
#define CC 10
#define HD 256      // H*D
#define MTILES 313  // ceil(40000/128)
#define MPAD (MTILES * 128)
#define SCAN_B 40

// ---------------- static device scratch ----------------
__device__ __half g_feat16[NN * HD];
__device__ float g_h1[NN * HD];
__device__ float g_h2[NN * HD];
__device__ float g_el[NN * HH];
__device__ float g_er[NN * HH];
__device__ float g_lmax[8];
__device__ float g_w[HH * EE];
__device__ int   g_counts[NN];
__device__ int   g_rowptr[NN + 1];
__device__ int   g_cursor[NN];
__device__ int   g_bsum[SCAN_B];
__device__ int   g_esrc[EE];
__device__ int   g_edst[EE];
__device__ float g_hg[GGR * DD];
__device__ float g_cnt[GGR];
__device__ __nv_bfloat16 g_Ahi[MPAD * HD];
__device__ __nv_bfloat16 g_Alo[MPAD * HD];
__device__ __nv_bfloat16 g_Bhi[HH * DD * HD];
__device__ __nv_bfloat16 g_Blo[HH * DD * HD];

__device__ __forceinline__ void atomicMaxFloat(float* addr, float value) {
    if (value >= 0.f)
        atomicMax((int*)addr, __float_as_int(value));
    else
        atomicMin((unsigned int*)addr, __float_as_uint(value));
}

__device__ __forceinline__ uint32_t pack_bf2(__nv_bfloat16 lo, __nv_bfloat16 hi) {
    return (uint32_t)__bfloat16_as_ushort(lo) | ((uint32_t)__bfloat16_as_ushort(hi) << 16);
}

__device__ __forceinline__ size_t a_frag_idx(int m, int k, int K) {
    int mt = m >> 4, rr = m & 15;
    int kt = k >> 4, cin = k & 15;
    int g = rr & 7;
    int r = (rr >> 3) | ((cin >> 3) << 1);
    int lane = g * 4 + ((cin & 6) >> 1);
    int tile = mt * (K >> 4) + kt;
    return ((size_t)(tile * 32 + lane) * 4 + r) * 2 + (cin & 1);
}

__device__ __forceinline__ void mma_bf16(float* c, const uint32_t* a, const uint32_t* b) {
    asm volatile(
        "mma.sync.aligned.m16n8k16.row.col.f32.bf16.bf16.f32 "
        "{%0,%1,%2,%3}, {%4,%5,%6,%7}, {%8,%9}, {%0,%1,%2,%3};"
        : "+f"(c[0]), "+f"(c[1]), "+f"(c[2]), "+f"(c[3])
        : "r"(a[0]), "r"(a[1]), "r"(a[2]), "r"(a[3]), "r"(b[0]), "r"(b[1]));
}

// ---------------- init + CSR build ----------------
__global__ void zero_kernel() {
    int t = blockIdx.x * blockDim.x + threadIdx.x;
    if (t < NN) { g_counts[t] = 0; g_cursor[t] = 0; }
    if (t < GGR * DD) g_hg[t] = 0.f;
    if (t < GGR) g_cnt[t] = 0.f;
}

__global__ void hist_kernel(const int* __restrict__ dst, const int* __restrict__ gid) {
    int t = blockIdx.x * blockDim.x + threadIdx.x;
    if (t < EE) atomicAdd(&g_counts[dst[t]], 1);
    if (t < NN) atomicAdd(&g_cnt[gid[t]], 1.0f);
}

__global__ void scan1_kernel() {
    __shared__ int sh[1024];
    int t = threadIdx.x;
    int idx = blockIdx.x * 1024 + t;
    int v = (idx < NN) ? g_counts[idx] : 0;
    sh[t] = v;
    __syncthreads();
    for (int off = 512; off; off >>= 1) {
        if (t < off) sh[t] += sh[t + off];
        __syncthreads();
    }
    if (t == 0) g_bsum[blockIdx.x] = sh[0];
}

__global__ void scan2_kernel() {
    int t = threadIdx.x;
    __shared__ int sh[64];
    int v = (t < SCAN_B) ? g_bsum[t] : 0;
    sh[t] = v;
    __syncthreads();
    for (int off = 1; off < 64; off <<= 1) {
        int add = (t >= off) ? sh[t - off] : 0;
        __syncthreads();
        sh[t] += add;
        __syncthreads();
    }
    if (t < SCAN_B) g_bsum[t] = sh[t] - v;
}

__global__ void scan3_kernel() {
    __shared__ int sh[1024];
    int t = threadIdx.x;
    int idx = blockIdx.x * 1024 + t;
    int v = (idx < NN) ? g_counts[idx] : 0;
    sh[t] = v;
    __syncthreads();
    for (int off = 1; off < 1024; off <<= 1) {
        int add = (t >= off) ? sh[t - off] : 0;
        __syncthreads();
        sh[t] += add;
        __syncthreads();
    }
    int off = g_bsum[blockIdx.x];
    if (idx < NN) g_rowptr[idx + 1] = off + sh[t];
    if (idx == 0) g_rowptr[0] = 0;
}

__global__ void scatter_kernel(const int* __restrict__ dst, const int* __restrict__ src) {
    int t = blockIdx.x * blockDim.x + threadIdx.x;
    if (t < EE) {
        int d = dst[t];
        int pos = g_rowptr[d] + atomicAdd(&g_cursor[d], 1);
        g_esrc[pos] = src[t];
        g_edst[pos] = d;
    }
}

// ---------------- prep kernels ----------------
__global__ void prep_x_kernel(const float* __restrict__ x) {
    const int KT = IN_DIM / 16;
    int idx = blockIdx.x * blockDim.x + threadIdx.x;
    int total = (MPAD / 16) * KT * 32;
    if (idx >= total) return;
    int lane = idx & 31;
    int tile = idx >> 5;
    int kt = tile % KT, mt = tile / KT;
    int g = lane >> 2, t2 = (lane & 3) * 2;
    uint32_t hi[4], lo[4];
#pragma unroll
    for (int r = 0; r < 4; r++) {
        int m = mt * 16 + g + ((r & 1) << 3);
        int k = kt * 16 + t2 + ((r >> 1) << 3);
        float v0 = (m < NN) ? x[(size_t)m * IN_DIM + k] : 0.f;
        float v1 = (m < NN) ? x[(size_t)m * IN_DIM + k + 1] : 0.f;
        __nv_bfloat16 h0 = __float2bfloat16(v0);
        __nv_bfloat16 h1 = __float2bfloat16(v1);
        __nv_bfloat16 l0 = __float2bfloat16(v0 - __bfloat162float(h0));
        __nv_bfloat16 l1 = __float2bfloat16(v1 - __bfloat162float(h1));
        hi[r] = pack_bf2(h0, h1);
        lo[r] = pack_bf2(l0, l1);
    }
    ((uint4*)g_Ahi)[tile * 32 + lane] = *(uint4*)hi;
    ((uint4*)g_Alo)[tile * 32 + lane] = *(uint4*)lo;
}

__global__ void prep_w_kernel(const float* __restrict__ W, int K) {
    int KT = K / 16;
    int idx = blockIdx.x * blockDim.x + threadIdx.x;
    if (idx < 8) g_lmax[idx] = -1e30f;
    int total = HH * KT * 8 * 32;
    if (idx >= total) return;
    int lane = idx & 31;
    int tile = idx >> 5;
    int nt = tile & 7;
    int hk = tile >> 3;
    int kt = hk % KT, h = hk / KT;
    int g = lane >> 2, t2 = (lane & 3) * 2;
    uint32_t hi[2], lo[2];
#pragma unroll
    for (int r = 0; r < 2; r++) {
        int k = kt * 16 + t2 + r * 8;
        int n = h * DD + nt * 8 + g;
        float v0 = W[(size_t)k * HD + n];
        float v1 = W[(size_t)(k + 1) * HD + n];
        __nv_bfloat16 h0 = __float2bfloat16(v0);
        __nv_bfloat16 h1 = __float2bfloat16(v1);
        __nv_bfloat16 l0 = __float2bfloat16(v0 - __bfloat162float(h0));
        __nv_bfloat16 l1 = __float2bfloat16(v1 - __bfloat162float(h1));
        hi[r] = pack_bf2(h0, h1);
        lo[r] = pack_bf2(l0, l1);
    }
    ((uint2*)g_Bhi)[tile * 32 + lane] = *(uint2*)hi;
    ((uint2*)g_Blo)[tile * 32 + lane] = *(uint2*)lo;
}

// ---------------- HMMA GEMM: smem-staged B (double-buffered) ----------------
template <int K>
__global__ void __launch_bounds__(256, 3)
hmma_gemm_kernel(const float* __restrict__ al, const float* __restrict__ arv) {
    const int KT = K / 16;
    __shared__ uint2 sB[2][2][8][32];   // [buf][hi/lo][nt][lane]
    __shared__ float al_s[64], ar_s[64];
    int tid = threadIdx.x, w = tid >> 5, lane = tid & 31;
    int h = blockIdx.x;
    int mt = blockIdx.y * 8 + w;
    if (tid < 64) al_s[tid] = al[h * DD + tid];
    else if (tid < 128) ar_s[tid - 64] = arv[h * DD + tid - 64];

    const uint4* Ah4 = (const uint4*)g_Ahi;
    const uint4* Al4 = (const uint4*)g_Alo;
    const uint2* Bh2 = (const uint2*)g_Bhi;
    const uint2* Bl2 = (const uint2*)g_Blo;

    // B loader role: warp w loads nt=w slice
    int tb_base = (h * KT * 8 + w) * 32 + lane;
    // prologue: kt=0 into buf 0
    sB[0][0][w][lane] = Bh2[tb_base];
    sB[0][1][w][lane] = Bl2[tb_base];
    __syncthreads();

    float acc[8][4] = {};
    uint2 nb_h, nb_l;
#pragma unroll 1
    for (int kt = 0; kt < KT; kt++) {
        int buf = kt & 1;
        if (kt + 1 < KT) {
            int tb = tb_base + (kt + 1) * 8 * 32;
            nb_h = Bh2[tb];
            nb_l = Bl2[tb];
        }
        uint4 a_h = Ah4[(mt * KT + kt) * 32 + lane];
        uint4 a_l = Al4[(mt * KT + kt) * 32 + lane];
#pragma unroll
        for (int nt = 0; nt < 8; nt++) {
            uint2 b_h = sB[buf][0][nt][lane];
            uint2 b_l = sB[buf][1][nt][lane];
            mma_bf16(acc[nt], (const uint32_t*)&a_h, (const uint32_t*)&b_h);
            mma_bf16(acc[nt], (const uint32_t*)&a_h, (const uint32_t*)&b_l);
            mma_bf16(acc[nt], (const uint32_t*)&a_l, (const uint32_t*)&b_h);
        }
        if (kt + 1 < KT) {
            sB[buf ^ 1][0][w][lane] = nb_h;
            sB[buf ^ 1][1][w][lane] = nb_l;
        }
        __syncthreads();
    }

    int g = lane >> 2, t2 = (lane & 3) * 2;
    int row0 = mt * 16 + g, row1 = row0 + 8;
    half2* F = (half2*)g_feat16;
    float el0 = 0.f, el1 = 0.f, er0 = 0.f, er1 = 0.f;
#pragma unroll
    for (int nt = 0; nt < 8; nt++) {
        int cb = nt * 8 + t2;
        float a0 = al_s[cb], a1 = al_s[cb + 1];
        float r0 = ar_s[cb], r1 = ar_s[cb + 1];
        el0 += acc[nt][0] * a0 + acc[nt][1] * a1;
        er0 += acc[nt][0] * r0 + acc[nt][1] * r1;
        el1 += acc[nt][2] * a0 + acc[nt][3] * a1;
        er1 += acc[nt][2] * r0 + acc[nt][3] * r1;
        int cidx = (h * DD + cb) >> 1;
        if (row0 < NN) F[row0 * (HD / 2) + cidx] = __floats2half2_rn(acc[nt][0], acc[nt][1]);
        if (row1 < NN) F[row1 * (HD / 2) + cidx] = __floats2half2_rn(acc[nt][2], acc[nt][3]);
    }
#pragma unroll
    for (int off = 1; off <= 2; off <<= 1) {
        el0 += __shfl_xor_sync(0xffffffffu, el0, off);
        el1 += __shfl_xor_sync(0xffffffffu, el1, off);
        er0 += __shfl_xor_sync(0xffffffffu, er0, off);
        er1 += __shfl_xor_sync(0xffffffffu, er1, off);
    }
    if ((lane & 3) == 0) {
        if (row0 < NN) { g_el[row0 * HH + h] = el0; g_er[row0 * HH + h] = er0; }
        if (row1 < NN) { g_el[row1 * HH + h] = el1; g_er[row1 * HH + h] = er1; }
    }
    float ml = fmaxf(row0 < NN ? el0 : -1e30f, row1 < NN ? el1 : -1e30f);
    float mr = fmaxf(row0 < NN ? er0 : -1e30f, row1 < NN ? er1 : -1e30f);
#pragma unroll
    for (int off = 16; off; off >>= 1) {
        ml = fmaxf(ml, __shfl_xor_sync(0xffffffffu, ml, off));
        mr = fmaxf(mr, __shfl_xor_sync(0xffffffffu, mr, off));
    }
    if (lane == 0) {
        atomicMaxFloat(&g_lmax[h], ml);
        atomicMaxFloat(&g_lmax[4 + h], mr);
    }
}

// ---------------- per-edge softmax weights ----------------
__global__ void wcalc_kernel() {
    int p = blockIdx.x * blockDim.x + threadIdx.x;
    if (p >= EE) return;
    int s = g_esrc[p], d = g_edst[p];
    float4 el = *(const float4*)&g_el[s * HH];
    float4 er = *(const float4*)&g_er[d * HH];
    float M0 = fmaxf(g_lmax[0] + g_lmax[4], 0.f);
    float M1 = fmaxf(g_lmax[1] + g_lmax[5], 0.f);
    float M2 = fmaxf(g_lmax[2] + g_lmax[6], 0.f);
    float M3 = fmaxf(g_lmax[3] + g_lmax[7], 0.f);
    float e0 = el.x + er.x, e1 = el.y + er.y, e2 = el.z + er.z, e3 = el.w + er.w;
    e0 = e0 > 0.f ? e0 : 0.2f * e0;
    e1 = e1 > 0.f ? e1 : 0.2f * e1;
    e2 = e2 > 0.f ? e2 : 0.2f * e2;
    e3 = e3 > 0.f ? e3 : 0.2f * e3;
    g_w[0 * EE + p] = __expf(e0 - M0);
    g_w[1 * EE + p] = __expf(e1 - M1);
    g_w[2 * EE + p] = __expf(e2 - M2);
    g_w[3 * EE + p] = __expf(e3 - M3);
}

// ---------------- aggregation core (R7 simple loop) ----------------
__device__ __forceinline__ void agg_node(int n, int h, int lane, const half2* F,
                                         float& o0, float& o1) {
    int s0 = __ldg(&g_rowptr[n]), s1 = __ldg(&g_rowptr[n + 1]);
    float a0 = 0.f, a1 = 0.f, sw = 0.f;
    for (int base = s0; base < s1; base += 32) {
        int cnt = min(32, s1 - base);
        int sidx = 0;
        float w = 0.f;
        if (lane < cnt) {
            sidx = __ldg(&g_esrc[base + lane]);
            w = __ldg(&g_w[h * EE + base + lane]);
        }
        sw += w;
#pragma unroll 8
        for (int j = 0; j < cnt; j++) {
            int sj = __shfl_sync(0xffffffffu, sidx, j);
            float wj = __shfl_sync(0xffffffffu, w, j);
            float2 vf = __half22float2(__ldg(&F[sj * (HD / 2) + h * 32 + lane]));
            a0 = fmaf(wj, vf.x, a0);
            a1 = fmaf(wj, vf.y, a1);
        }
    }
#pragma unroll
    for (int off = 16; off; off >>= 1)
        sw += __shfl_xor_sync(0xffffffffu, sw, off);
    float inv = 1.f / fmaxf(sw, 1e-9f);
    o0 = a0 * inv;
    o1 = a1 * inv;
}

// ---------------- aggregation (layers 0/1) ----------------
__global__ void __launch_bounds__(256, 6)
agg_kernel(const float* __restrict__ hin, float* __restrict__ hout,
           int residual, int activate) {
    int n = blockIdx.x * 2 + (threadIdx.x >> 7);
    int h = (threadIdx.x >> 5) & 3;
    int lane = threadIdx.x & 31;
    const half2* F = (const half2*)g_feat16;

    float o0 = 0.f, o1 = 0.f;
    if (n < NN) {
        agg_node(n, h, lane, F, o0, o1);
        size_t outb = (size_t)n * HD + h * DD + 2 * lane;
        if (residual) {
            float2 r = *(const float2*)&hin[outb];
            o0 += r.x;
            o1 += r.y;
        }
        if (activate) {
            o0 = o0 > 0.f ? o0 : (__expf(o0) - 1.f);
            o1 = o1 > 0.f ? o1 : (__expf(o1) - 1.f);
        }
        *(float2*)&hout[outb] = make_float2(o0, o1);
    }
    if (n < MPAD) {
        int k0 = h * DD + 2 * lane;
        size_t i0 = a_frag_idx(n, k0, HD);
        __nv_bfloat16 h0 = __float2bfloat16(o0);
        __nv_bfloat16 l0 = __float2bfloat16(o0 - __bfloat162float(h0));
        __nv_bfloat16 h1 = __float2bfloat16(o1);
        __nv_bfloat16 l1 = __float2bfloat16(o1 - __bfloat162float(h1));
        ((uint32_t*)g_Ahi)[i0 >> 1] = pack_bf2(h0, h1);
        ((uint32_t*)g_Alo)[i0 >> 1] = pack_bf2(l0, l1);
    }
}

// ---------------- layer-2 aggregation fused with readout ----------------
__global__ void __launch_bounds__(256, 6)
agg_final_kernel(const float* __restrict__ hin, const int* __restrict__ gid) {
    __shared__ float red[2][HH][DD];
    int half = threadIdx.x >> 7;
    int n = blockIdx.x * 2 + half;
    int h = (threadIdx.x >> 5) & 3;
    int lane = threadIdx.x & 31;
    const half2* F = (const half2*)g_feat16;

    float o0 = 0.f, o1 = 0.f;
    if (n < NN) {
        agg_node(n, h, lane, F, o0, o1);
        size_t outb = (size_t)n * HD + h * DD + 2 * lane;
        float2 r = *(const float2*)&hin[outb];
        o0 += r.x;
        o1 += r.y;
    }
    red[half][h][2 * lane] = o0;
    red[half][h][2 * lane + 1] = o1;
    __syncthreads();
    if (h == 0 && n < NN) {
        int g = __ldg(&gid[n]);
        float s0 = 0.25f * (red[half][0][2 * lane] + red[half][1][2 * lane] +
                            red[half][2][2 * lane] + red[half][3][2 * lane]);
        float s1 = 0.25f * (red[half][0][2 * lane + 1] + red[half][1][2 * lane + 1] +
                            red[half][2][2 * lane + 1] + red[half][3][2 * lane + 1]);
        atomicAdd(&g_hg[g * DD + 2 * lane], s0);
        atomicAdd(&g_hg[g * DD + 2 * lane + 1], s1);
    }
}

__global__ void classifier_kernel(const float* __restrict__ Wc, const float* __restrict__ bc,
                                  float* __restrict__ out) {
    int t = threadIdx.x;
    if (t >= GGR * CC) return;
    int g = t / CC, c = t % CC;
    float s = 0.f;
#pragma unroll
    for (int d = 0; d < DD; d++) s += g_hg[g * DD + d] * Wc[d * CC + c];
    out[t] = s / fmaxf(g_cnt[g], 1.0f) + bc[c];
}

// ---------------- host ----------------
extern "C" void kernel_launch(void* const* d_in, const int* in_sizes, int n_in,
                              void* d_out, int out_size) {
    const float* x   = (const float*)d_in[0];
    const int*   src = (const int*)d_in[1];
    const int*   dst = (const int*)d_in[2];
    const int*   gid = (const int*)d_in[3];
    const float* W0  = (const float*)d_in[4];
    const float* al0 = (const float*)d_in[5];
    const float* ar0 = (const float*)d_in[6];
    const float* W1  = (const float*)d_in[7];
    const float* al1 = (const float*)d_in[8];
    const float* ar1 = (const float*)d_in[9];
    const float* W2  = (const float*)d_in[10];
    const float* al2 = (const float*)d_in[11];
    const float* ar2 = (const float*)d_in[12];
    const float* Wc  = (const float*)d_in[13];
    const float* bc  = (const float*)d_in[14];
    float* out = (float*)d_out;

    void *p_h1, *p_h2;
    cudaGetSymbolAddress(&p_h1, g_h1);
    cudaGetSymbolAddress(&p_h2, g_h2);
    float* f_h1 = (float*)p_h1;
    float* f_h2 = (float*)p_h2;

    dim3 mgrid(HH, MTILES);

    prep_x_kernel<<<((MPAD / 16) * (IN_DIM / 16) * 32 + 255) / 256, 256>>>(x);     // 0
    prep_w_kernel<<<(HH * (IN_DIM / 16) * 8 * 32 + 255) / 256, 256>>>(W0, IN_DIM); // 1
    zero_kernel<<<(NN + 255) / 256, 256>>>();                                       // 2
    hmma_gemm_kernel<IN_DIM><<<mgrid, 256>>>(al0, ar0);                             // 3 <- ncu capture
    // CSR build
    hist_kernel<<<(EE + 255) / 256, 256>>>(dst, gid);
    scan1_kernel<<<SCAN_B, 1024>>>();
    scan2_kernel<<<1, 64>>>();
    scan3_kernel<<<SCAN_B, 1024>>>();
    scatter_kernel<<<(EE + 255) / 256, 256>>>(dst, src);

    // ---- layer 0 tail ----
    wcalc_kernel<<<(EE + 255) / 256, 256>>>();
    agg_kernel<<<MPAD / 2, 256>>>(nullptr, f_h1, 0, 1);

    // ---- layer 1 ----
    prep_w_kernel<<<(HH * (HD / 16) * 8 * 32 + 255) / 256, 256>>>(W1, HD);
    hmma_gemm_kernel<HD><<<mgrid, 256>>>(al1, ar1);
    wcalc_kernel<<<(EE + 255) / 256, 256>>>();
    agg_kernel<<<MPAD / 2, 256>>>(f_h1, f_h2, 1, 1);

    // ---- layer 2 + fused readout ----
    prep_w_kernel<<<(HH * (HD / 16) * 8 * 32 + 255) / 256, 256>>>(W2, HD);
    hmma_gemm_kernel<HD><<<mgrid, 256>>>(al2, ar2);
    wcalc_kernel<<<(EE + 255) / 256, 256>>>();
    agg_final_kernel<<<(NN + 1) / 2, 256>>>(f_h2, gid);

    // ---- classifier ----
    classifier_kernel<<<1, GGR * CC>>>(Wc, bc, out);
}

// round 10
// speedup vs baseline: 1.1399x; 1.1399x over previous
#include <cuda_runtime.h>
#include <cuda_bf16.h>
#include <cuda_fp16.h>
#include <cstdint>

#define NN 40000
#define EE 400000
#define GGR 64
#define IN_DIM 128
#define DD 64
#define HH 4
#define CC 10
#define HD 256      // H*D
#define MTILES 313  // ceil(40000/128)
#define MPAD (MTILES * 128)
#define SCAN_B 40

// ---------------- static device scratch ----------------
__device__ __half g_feat16[NN * HD];
__device__ float g_h1[NN * HD];
__device__ float g_h2[NN * HD];
__device__ float g_el[NN * HH];
__device__ float g_er[NN * HH];
__device__ float g_lmax[8];
__device__ float g_w[HH * EE];
__device__ int   g_counts[NN];
__device__ int   g_rowptr[NN + 1];
__device__ int   g_cursor[NN];
__device__ int   g_bsum[SCAN_B];
__device__ int   g_esrc[EE];
__device__ int   g_edst[EE];
__device__ float g_hg[GGR * DD];
__device__ float g_cnt[GGR];
__device__ __nv_bfloat16 g_Ahi[MPAD * HD];
__device__ __nv_bfloat16 g_Alo[MPAD * HD];
__device__ __nv_bfloat16 g_Bhi[HH * DD * HD];
__device__ __nv_bfloat16 g_Blo[HH * DD * HD];

__device__ __forceinline__ void atomicMaxFloat(float* addr, float value) {
    if (value >= 0.f)
        atomicMax((int*)addr, __float_as_int(value));
    else
        atomicMin((unsigned int*)addr, __float_as_uint(value));
}

__device__ __forceinline__ uint32_t pack_bf2(__nv_bfloat16 lo, __nv_bfloat16 hi) {
    return (uint32_t)__bfloat16_as_ushort(lo) | ((uint32_t)__bfloat16_as_ushort(hi) << 16);
}

__device__ __forceinline__ size_t a_frag_idx(int m, int k, int K) {
    int mt = m >> 4, rr = m & 15;
    int kt = k >> 4, cin = k & 15;
    int g = rr & 7;
    int r = (rr >> 3) | ((cin >> 3) << 1);
    int lane = g * 4 + ((cin & 6) >> 1);
    int tile = mt * (K >> 4) + kt;
    return ((size_t)(tile * 32 + lane) * 4 + r) * 2 + (cin & 1);
}

__device__ __forceinline__ void mma_bf16(float* c, const uint32_t* a, const uint32_t* b) {
    asm volatile(
        "mma.sync.aligned.m16n8k16.row.col.f32.bf16.bf16.f32 "
        "{%0,%1,%2,%3}, {%4,%5,%6,%7}, {%8,%9}, {%0,%1,%2,%3};"
        : "+f"(c[0]), "+f"(c[1]), "+f"(c[2]), "+f"(c[3])
        : "r"(a[0]), "r"(a[1]), "r"(a[2]), "r"(a[3]), "r"(b[0]), "r"(b[1]));
}

// ---------------- init + CSR build (R7 verbatim) ----------------
__global__ void zero_kernel() {
    int t = blockIdx.x * blockDim.x + threadIdx.x;
    if (t < NN) { g_counts[t] = 0; g_cursor[t] = 0; }
    if (t < GGR * DD) g_hg[t] = 0.f;
    if (t < GGR) g_cnt[t] = 0.f;
}

__global__ void hist_kernel(const int* __restrict__ dst) {
    int t = blockIdx.x * blockDim.x + threadIdx.x;
    if (t < EE) atomicAdd(&g_counts[dst[t]], 1);
}

__global__ void scan1_kernel() {
    __shared__ int sh[1024];
    int t = threadIdx.x;
    int idx = blockIdx.x * 1024 + t;
    int v = (idx < NN) ? g_counts[idx] : 0;
    sh[t] = v;
    __syncthreads();
    for (int off = 512; off; off >>= 1) {
        if (t < off) sh[t] += sh[t + off];
        __syncthreads();
    }
    if (t == 0) g_bsum[blockIdx.x] = sh[0];
}

__global__ void scan2_kernel() {
    int t = threadIdx.x;
    __shared__ int sh[64];
    int v = (t < SCAN_B) ? g_bsum[t] : 0;
    sh[t] = v;
    __syncthreads();
    for (int off = 1; off < 64; off <<= 1) {
        int add = (t >= off) ? sh[t - off] : 0;
        __syncthreads();
        sh[t] += add;
        __syncthreads();
    }
    if (t < SCAN_B) g_bsum[t] = sh[t] - v;
}

__global__ void scan3_kernel() {
    __shared__ int sh[1024];
    int t = threadIdx.x;
    int idx = blockIdx.x * 1024 + t;
    int v = (idx < NN) ? g_counts[idx] : 0;
    sh[t] = v;
    __syncthreads();
    for (int off = 1; off < 1024; off <<= 1) {
        int add = (t >= off) ? sh[t - off] : 0;
        __syncthreads();
        sh[t] += add;
        __syncthreads();
    }
    int off = g_bsum[blockIdx.x];
    if (idx < NN) g_rowptr[idx + 1] = off + sh[t];
    if (idx == 0) g_rowptr[0] = 0;
}

__global__ void scatter_kernel(const int* __restrict__ dst, const int* __restrict__ src) {
    int t = blockIdx.x * blockDim.x + threadIdx.x;
    if (t < EE) {
        int d = dst[t];
        int pos = g_rowptr[d] + atomicAdd(&g_cursor[d], 1);
        g_esrc[pos] = src[t];
        g_edst[pos] = d;
    }
}

// ---------------- prep kernels (R7 verbatim) ----------------
__global__ void prep_x_kernel(const float* __restrict__ x) {
    const int KT = IN_DIM / 16;
    int idx = blockIdx.x * blockDim.x + threadIdx.x;
    int total = (MPAD / 16) * KT * 32;
    if (idx >= total) return;
    int lane = idx & 31;
    int tile = idx >> 5;
    int kt = tile % KT, mt = tile / KT;
    int g = lane >> 2, t2 = (lane & 3) * 2;
    uint32_t hi[4], lo[4];
#pragma unroll
    for (int r = 0; r < 4; r++) {
        int m = mt * 16 + g + ((r & 1) << 3);
        int k = kt * 16 + t2 + ((r >> 1) << 3);
        float v0 = (m < NN) ? x[(size_t)m * IN_DIM + k] : 0.f;
        float v1 = (m < NN) ? x[(size_t)m * IN_DIM + k + 1] : 0.f;
        __nv_bfloat16 h0 = __float2bfloat16(v0);
        __nv_bfloat16 h1 = __float2bfloat16(v1);
        __nv_bfloat16 l0 = __float2bfloat16(v0 - __bfloat162float(h0));
        __nv_bfloat16 l1 = __float2bfloat16(v1 - __bfloat162float(h1));
        hi[r] = pack_bf2(h0, h1);
        lo[r] = pack_bf2(l0, l1);
    }
    ((uint4*)g_Ahi)[tile * 32 + lane] = *(uint4*)hi;
    ((uint4*)g_Alo)[tile * 32 + lane] = *(uint4*)lo;
}

__global__ void prep_w_kernel(const float* __restrict__ W, int K) {
    int KT = K / 16;
    int idx = blockIdx.x * blockDim.x + threadIdx.x;
    if (idx < 8) g_lmax[idx] = -1e30f;
    int total = HH * KT * 8 * 32;
    if (idx >= total) return;
    int lane = idx & 31;
    int tile = idx >> 5;
    int nt = tile & 7;
    int hk = tile >> 3;
    int kt = hk % KT, h = hk / KT;
    int g = lane >> 2, t2 = (lane & 3) * 2;
    uint32_t hi[2], lo[2];
#pragma unroll
    for (int r = 0; r < 2; r++) {
        int k = kt * 16 + t2 + r * 8;
        int n = h * DD + nt * 8 + g;
        float v0 = W[(size_t)k * HD + n];
        float v1 = W[(size_t)(k + 1) * HD + n];
        __nv_bfloat16 h0 = __float2bfloat16(v0);
        __nv_bfloat16 h1 = __float2bfloat16(v1);
        __nv_bfloat16 l0 = __float2bfloat16(v0 - __bfloat162float(h0));
        __nv_bfloat16 l1 = __float2bfloat16(v1 - __bfloat162float(h1));
        hi[r] = pack_bf2(h0, h1);
        lo[r] = pack_bf2(l0, l1);
    }
    ((uint2*)g_Bhi)[tile * 32 + lane] = *(uint2*)hi;
    ((uint2*)g_Blo)[tile * 32 + lane] = *(uint2*)lo;
}

// ---------------- HMMA GEMM: 2 heads per CTA (N=128), 2x MMA ILP per A load ----------------
template <int K>
__global__ void __launch_bounds__(256, 2)
hmma_gemm_kernel(const float* __restrict__ al, const float* __restrict__ arv) {
    const int KT = K / 16;
    __shared__ float al_s[2][64], ar_s[2][64];
    int tid = threadIdx.x, w = tid >> 5, lane = tid & 31;
    int h0 = blockIdx.x * 2;
    int mt = blockIdx.y * 8 + w;
    if (tid < 128) al_s[tid >> 6][tid & 63] = al[h0 * DD + tid];
    else ar_s[(tid - 128) >> 6][tid & 63] = arv[h0 * DD + tid - 128];
    __syncthreads();

    const uint4* Ah4 = (const uint4*)g_Ahi;
    const uint4* Al4 = (const uint4*)g_Alo;
    const uint2* Bh2 = (const uint2*)g_Bhi;
    const uint2* Bl2 = (const uint2*)g_Blo;

    float acc[16][4] = {};
#pragma unroll 1
    for (int kt = 0; kt < KT; kt++) {
        uint4 a_h = Ah4[(mt * KT + kt) * 32 + lane];
        uint4 a_l = Al4[(mt * KT + kt) * 32 + lane];
#pragma unroll
        for (int hh = 0; hh < 2; hh++) {
            int tb = (((h0 + hh) * KT + kt) * 8) * 32 + lane;
#pragma unroll
            for (int nt = 0; nt < 8; nt++) {
                uint2 b_h = Bh2[tb + nt * 32];
                uint2 b_l = Bl2[tb + nt * 32];
                mma_bf16(acc[hh * 8 + nt], (const uint32_t*)&a_h, (const uint32_t*)&b_h);
                mma_bf16(acc[hh * 8 + nt], (const uint32_t*)&a_h, (const uint32_t*)&b_l);
                mma_bf16(acc[hh * 8 + nt], (const uint32_t*)&a_l, (const uint32_t*)&b_h);
            }
        }
    }

    int g = lane >> 2, t2 = (lane & 3) * 2;
    int row0 = mt * 16 + g, row1 = row0 + 8;
    half2* F = (half2*)g_feat16;
#pragma unroll
    for (int hh = 0; hh < 2; hh++) {
        int h = h0 + hh;
        float el0 = 0.f, el1 = 0.f, er0 = 0.f, er1 = 0.f;
#pragma unroll
        for (int nt = 0; nt < 8; nt++) {
            float* a4 = acc[hh * 8 + nt];
            int cb = nt * 8 + t2;
            float a0 = al_s[hh][cb], a1 = al_s[hh][cb + 1];
            float r0 = ar_s[hh][cb], r1 = ar_s[hh][cb + 1];
            el0 += a4[0] * a0 + a4[1] * a1;
            er0 += a4[0] * r0 + a4[1] * r1;
            el1 += a4[2] * a0 + a4[3] * a1;
            er1 += a4[2] * r0 + a4[3] * r1;
            int cidx = (h * DD + cb) >> 1;
            if (row0 < NN) F[row0 * (HD / 2) + cidx] = __floats2half2_rn(a4[0], a4[1]);
            if (row1 < NN) F[row1 * (HD / 2) + cidx] = __floats2half2_rn(a4[2], a4[3]);
        }
#pragma unroll
        for (int off = 1; off <= 2; off <<= 1) {
            el0 += __shfl_xor_sync(0xffffffffu, el0, off);
            el1 += __shfl_xor_sync(0xffffffffu, el1, off);
            er0 += __shfl_xor_sync(0xffffffffu, er0, off);
            er1 += __shfl_xor_sync(0xffffffffu, er1, off);
        }
        if ((lane & 3) == 0) {
            if (row0 < NN) { g_el[row0 * HH + h] = el0; g_er[row0 * HH + h] = er0; }
            if (row1 < NN) { g_el[row1 * HH + h] = el1; g_er[row1 * HH + h] = er1; }
        }
        float ml = fmaxf(row0 < NN ? el0 : -1e30f, row1 < NN ? el1 : -1e30f);
        float mr = fmaxf(row0 < NN ? er0 : -1e30f, row1 < NN ? er1 : -1e30f);
#pragma unroll
        for (int off = 16; off; off >>= 1) {
            ml = fmaxf(ml, __shfl_xor_sync(0xffffffffu, ml, off));
            mr = fmaxf(mr, __shfl_xor_sync(0xffffffffu, mr, off));
        }
        if (lane == 0) {
            atomicMaxFloat(&g_lmax[h], ml);
            atomicMaxFloat(&g_lmax[4 + h], mr);
        }
    }
}

// ---------------- per-edge softmax weights (R7 verbatim) ----------------
__global__ void wcalc_kernel() {
    int p = blockIdx.x * blockDim.x + threadIdx.x;
    if (p >= EE) return;
    int s = g_esrc[p], d = g_edst[p];
    float4 el = *(const float4*)&g_el[s * HH];
    float4 er = *(const float4*)&g_er[d * HH];
    float M0 = fmaxf(g_lmax[0] + g_lmax[4], 0.f);
    float M1 = fmaxf(g_lmax[1] + g_lmax[5], 0.f);
    float M2 = fmaxf(g_lmax[2] + g_lmax[6], 0.f);
    float M3 = fmaxf(g_lmax[3] + g_lmax[7], 0.f);
    float e0 = el.x + er.x, e1 = el.y + er.y, e2 = el.z + er.z, e3 = el.w + er.w;
    e0 = e0 > 0.f ? e0 : 0.2f * e0;
    e1 = e1 > 0.f ? e1 : 0.2f * e1;
    e2 = e2 > 0.f ? e2 : 0.2f * e2;
    e3 = e3 > 0.f ? e3 : 0.2f * e3;
    g_w[0 * EE + p] = __expf(e0 - M0);
    g_w[1 * EE + p] = __expf(e1 - M1);
    g_w[2 * EE + p] = __expf(e2 - M2);
    g_w[3 * EE + p] = __expf(e3 - M3);
}

// ---------------- aggregation (R7 verbatim) ----------------
__global__ void __launch_bounds__(256, 6)
agg_kernel(const float* __restrict__ hin, float* __restrict__ hout,
           int residual, int activate, int write_bf16) {
    int n = blockIdx.x * 2 + (threadIdx.x >> 7);
    int h = (threadIdx.x >> 5) & 3;
    int lane = threadIdx.x & 31;
    const half2* F = (const half2*)g_feat16;

    float o0 = 0.f, o1 = 0.f;
    if (n < NN) {
        int s0 = __ldg(&g_rowptr[n]), s1 = __ldg(&g_rowptr[n + 1]);
        float a0 = 0.f, a1 = 0.f, sw = 0.f;
        for (int base = s0; base < s1; base += 32) {
            int cnt = min(32, s1 - base);
            int sidx = 0;
            float w = 0.f;
            if (lane < cnt) {
                sidx = __ldg(&g_esrc[base + lane]);
                w = __ldg(&g_w[h * EE + base + lane]);
            }
            sw += w;
#pragma unroll 8
            for (int j = 0; j < cnt; j++) {
                int sj = __shfl_sync(0xffffffffu, sidx, j);
                float wj = __shfl_sync(0xffffffffu, w, j);
                float2 vf = __half22float2(__ldg(&F[sj * (HD / 2) + h * 32 + lane]));
                a0 = fmaf(wj, vf.x, a0);
                a1 = fmaf(wj, vf.y, a1);
            }
        }
#pragma unroll
        for (int off = 16; off; off >>= 1)
            sw += __shfl_xor_sync(0xffffffffu, sw, off);
        float inv = 1.f / fmaxf(sw, 1e-9f);
        o0 = a0 * inv;
        o1 = a1 * inv;
        size_t outb = (size_t)n * HD + h * DD + 2 * lane;
        if (residual) {
            float2 r = *(const float2*)&hin[outb];
            o0 += r.x;
            o1 += r.y;
        }
        if (activate) {
            o0 = o0 > 0.f ? o0 : (__expf(o0) - 1.f);
            o1 = o1 > 0.f ? o1 : (__expf(o1) - 1.f);
        }
        *(float2*)&hout[outb] = make_float2(o0, o1);
    }
    if (write_bf16 && n < MPAD) {
        int k0 = h * DD + 2 * lane;
        size_t i0 = a_frag_idx(n, k0, HD);
        __nv_bfloat16 h0 = __float2bfloat16(o0);
        __nv_bfloat16 l0 = __float2bfloat16(o0 - __bfloat162float(h0));
        __nv_bfloat16 h1 = __float2bfloat16(o1);
        __nv_bfloat16 l1 = __float2bfloat16(o1 - __bfloat162float(h1));
        ((uint32_t*)g_Ahi)[i0 >> 1] = pack_bf2(h0, h1);
        ((uint32_t*)g_Alo)[i0 >> 1] = pack_bf2(l0, l1);
    }
}

// ---------------- readout + classifier (R7 verbatim) ----------------
__global__ void readout_kernel(const float* __restrict__ hfin, const int* __restrict__ gid) {
    int warp = threadIdx.x >> 5;
    int lane = threadIdx.x & 31;
    int base_n = (blockIdx.x * 8 + warp) * 8;
    if (base_n >= NN) return;
    float acc0 = 0.f, acc1 = 0.f;
    int cur = gid[base_n];
    int cnt = 0;
#pragma unroll
    for (int k = 0; k < 8; k++) {
        int n = base_n + k;
        if (n >= NN) break;
        int g = gid[n];
        if (g != cur) {
            atomicAdd(&g_hg[cur * DD + lane], acc0);
            atomicAdd(&g_hg[cur * DD + lane + 32], acc1);
            if (lane == 0) atomicAdd(&g_cnt[cur], (float)cnt);
            cur = g; acc0 = acc1 = 0.f; cnt = 0;
        }
        const float* f = &hfin[(size_t)n * HD];
        acc0 += 0.25f * (f[lane] + f[DD + lane] + f[2 * DD + lane] + f[3 * DD + lane]);
        acc1 += 0.25f * (f[lane + 32] + f[DD + lane + 32] + f[2 * DD + lane + 32] + f[3 * DD + lane + 32]);
        cnt++;
    }
    atomicAdd(&g_hg[cur * DD + lane], acc0);
    atomicAdd(&g_hg[cur * DD + lane + 32], acc1);
    if (lane == 0) atomicAdd(&g_cnt[cur], (float)cnt);
}

__global__ void classifier_kernel(const float* __restrict__ Wc, const float* __restrict__ bc,
                                  float* __restrict__ out) {
    int t = threadIdx.x;
    if (t >= GGR * CC) return;
    int g = t / CC, c = t % CC;
    float s = 0.f;
#pragma unroll
    for (int d = 0; d < DD; d++) s += g_hg[g * DD + d] * Wc[d * CC + c];
    out[t] = s / fmaxf(g_cnt[g], 1.0f) + bc[c];
}

// ---------------- host ----------------
extern "C" void kernel_launch(void* const* d_in, const int* in_sizes, int n_in,
                              void* d_out, int out_size) {
    const float* x   = (const float*)d_in[0];
    const int*   src = (const int*)d_in[1];
    const int*   dst = (const int*)d_in[2];
    const int*   gid = (const int*)d_in[3];
    const float* W0  = (const float*)d_in[4];
    const float* al0 = (const float*)d_in[5];
    const float* ar0 = (const float*)d_in[6];
    const float* W1  = (const float*)d_in[7];
    const float* al1 = (const float*)d_in[8];
    const float* ar1 = (const float*)d_in[9];
    const float* W2  = (const float*)d_in[10];
    const float* al2 = (const float*)d_in[11];
    const float* ar2 = (const float*)d_in[12];
    const float* Wc  = (const float*)d_in[13];
    const float* bc  = (const float*)d_in[14];
    float* out = (float*)d_out;

    void *p_h1, *p_h2;
    cudaGetSymbolAddress(&p_h1, g_h1);
    cudaGetSymbolAddress(&p_h2, g_h2);
    float* f_h1 = (float*)p_h1;
    float* f_h2 = (float*)p_h2;

    dim3 mgrid(HH / 2, MTILES);   // 2 heads per CTA

    prep_x_kernel<<<((MPAD / 16) * (IN_DIM / 16) * 32 + 255) / 256, 256>>>(x);     // 0
    prep_w_kernel<<<(HH * (IN_DIM / 16) * 8 * 32 + 255) / 256, 256>>>(W0, IN_DIM); // 1
    zero_kernel<<<(NN + 255) / 256, 256>>>();                                       // 2
    hmma_gemm_kernel<IN_DIM><<<mgrid, 256>>>(al0, ar0);                             // 3 <- ncu capture
    // CSR build
    hist_kernel<<<(EE + 255) / 256, 256>>>(dst);
    scan1_kernel<<<SCAN_B, 1024>>>();
    scan2_kernel<<<1, 64>>>();
    scan3_kernel<<<SCAN_B, 1024>>>();
    scatter_kernel<<<(EE + 255) / 256, 256>>>(dst, src);

    // ---- layer 0 tail ----
    wcalc_kernel<<<(EE + 255) / 256, 256>>>();
    agg_kernel<<<MPAD / 2, 256>>>(nullptr, f_h1, 0, 1, 1);

    // ---- layer 1 ----
    prep_w_kernel<<<(HH * (HD / 16) * 8 * 32 + 255) / 256, 256>>>(W1, HD);
    hmma_gemm_kernel<HD><<<mgrid, 256>>>(al1, ar1);
    wcalc_kernel<<<(EE + 255) / 256, 256>>>();
    agg_kernel<<<MPAD / 2, 256>>>(f_h1, f_h2, 1, 1, 1);

    // ---- layer 2 ----
    prep_w_kernel<<<(HH * (HD / 16) * 8 * 32 + 255) / 256, 256>>>(W2, HD);
    hmma_gemm_kernel<HD><<<mgrid, 256>>>(al2, ar2);
    wcalc_kernel<<<(EE + 255) / 256, 256>>>();
    agg_kernel<<<(NN + 1) / 2, 256>>>(f_h2, f_h1, 1, 0, 0);

    // ---- readout + classifier ----
    readout_kernel<<<(NN + 63) / 64, 256>>>(f_h1, gid);
    classifier_kernel<<<1, GGR * CC>>>(Wc, bc, out);
}

// round 11
// speedup vs baseline: 1.1622x; 1.0195x over previous
#include <cuda_runtime.h>
#include <cuda_bf16.h>
#include <cuda_fp16.h>
#include <cstdint>

#define NN 40000
#define EE 400000
#define GGR 64
#define IN_DIM 128
#define DD 64
#define HH 4
#define CC 10
#define HD 256      // H*D
#define MTILES 313  // ceil(40000/128)
#define MPAD (MTILES * 128)
#define NATOM (MPAD / 16)   // 2504 sixteen-row atoms
#define SCAN_B 40

// ---------------- static device scratch ----------------
__device__ __half g_feat16[NN * HD];
__device__ float g_h1[NN * HD];
__device__ float g_h2[NN * HD];
__device__ float g_el[NN * HH];
__device__ float g_er[NN * HH];
__device__ float g_lmax[8];
__device__ float g_w[HH * EE];
__device__ int   g_counts[NN];
__device__ int   g_rowptr[NN + 1];
__device__ int   g_cursor[NN];
__device__ int   g_bsum[SCAN_B];
__device__ int   g_esrc[EE];
__device__ int   g_edst[EE];
__device__ float g_hg[GGR * DD];
__device__ float g_cnt[GGR];
__device__ __nv_bfloat16 g_Ahi[MPAD * HD];
__device__ __nv_bfloat16 g_Alo[MPAD * HD];
__device__ __nv_bfloat16 g_Bhi[HH * DD * HD];
__device__ __nv_bfloat16 g_Blo[HH * DD * HD];

__device__ __forceinline__ void atomicMaxFloat(float* addr, float value) {
    if (value >= 0.f)
        atomicMax((int*)addr, __float_as_int(value));
    else
        atomicMin((unsigned int*)addr, __float_as_uint(value));
}

__device__ __forceinline__ uint32_t pack_bf2(__nv_bfloat16 lo, __nv_bfloat16 hi) {
    return (uint32_t)__bfloat16_as_ushort(lo) | ((uint32_t)__bfloat16_as_ushort(hi) << 16);
}

__device__ __forceinline__ size_t a_frag_idx(int m, int k, int K) {
    int mt = m >> 4, rr = m & 15;
    int kt = k >> 4, cin = k & 15;
    int g = rr & 7;
    int r = (rr >> 3) | ((cin >> 3) << 1);
    int lane = g * 4 + ((cin & 6) >> 1);
    int tile = mt * (K >> 4) + kt;
    return ((size_t)(tile * 32 + lane) * 4 + r) * 2 + (cin & 1);
}

__device__ __forceinline__ void mma_bf16(float* c, const uint32_t* a, const uint32_t* b) {
    asm volatile(
        "mma.sync.aligned.m16n8k16.row.col.f32.bf16.bf16.f32 "
        "{%0,%1,%2,%3}, {%4,%5,%6,%7}, {%8,%9}, {%0,%1,%2,%3};"
        : "+f"(c[0]), "+f"(c[1]), "+f"(c[2]), "+f"(c[3])
        : "r"(a[0]), "r"(a[1]), "r"(a[2]), "r"(a[3]), "r"(b[0]), "r"(b[1]));
}

// ---------------- init + CSR build (R7 verbatim) ----------------
__global__ void zero_kernel() {
    int t = blockIdx.x * blockDim.x + threadIdx.x;
    if (t < NN) { g_counts[t] = 0; g_cursor[t] = 0; }
    if (t < GGR * DD) g_hg[t] = 0.f;
    if (t < GGR) g_cnt[t] = 0.f;
}

__global__ void hist_kernel(const int* __restrict__ dst) {
    int t = blockIdx.x * blockDim.x + threadIdx.x;
    if (t < EE) atomicAdd(&g_counts[dst[t]], 1);
}

__global__ void scan1_kernel() {
    __shared__ int sh[1024];
    int t = threadIdx.x;
    int idx = blockIdx.x * 1024 + t;
    int v = (idx < NN) ? g_counts[idx] : 0;
    sh[t] = v;
    __syncthreads();
    for (int off = 512; off; off >>= 1) {
        if (t < off) sh[t] += sh[t + off];
        __syncthreads();
    }
    if (t == 0) g_bsum[blockIdx.x] = sh[0];
}

__global__ void scan2_kernel() {
    int t = threadIdx.x;
    __shared__ int sh[64];
    int v = (t < SCAN_B) ? g_bsum[t] : 0;
    sh[t] = v;
    __syncthreads();
    for (int off = 1; off < 64; off <<= 1) {
        int add = (t >= off) ? sh[t - off] : 0;
        __syncthreads();
        sh[t] += add;
        __syncthreads();
    }
    if (t < SCAN_B) g_bsum[t] = sh[t] - v;
}

__global__ void scan3_kernel() {
    __shared__ int sh[1024];
    int t = threadIdx.x;
    int idx = blockIdx.x * 1024 + t;
    int v = (idx < NN) ? g_counts[idx] : 0;
    sh[t] = v;
    __syncthreads();
    for (int off = 1; off < 1024; off <<= 1) {
        int add = (t >= off) ? sh[t - off] : 0;
        __syncthreads();
        sh[t] += add;
        __syncthreads();
    }
    int off = g_bsum[blockIdx.x];
    if (idx < NN) g_rowptr[idx + 1] = off + sh[t];
    if (idx == 0) g_rowptr[0] = 0;
}

__global__ void scatter_kernel(const int* __restrict__ dst, const int* __restrict__ src) {
    int t = blockIdx.x * blockDim.x + threadIdx.x;
    if (t < EE) {
        int d = dst[t];
        int pos = g_rowptr[d] + atomicAdd(&g_cursor[d], 1);
        g_esrc[pos] = src[t];
        g_edst[pos] = d;
    }
}

// ---------------- prep kernels (R7 verbatim) ----------------
__global__ void prep_x_kernel(const float* __restrict__ x) {
    const int KT = IN_DIM / 16;
    int idx = blockIdx.x * blockDim.x + threadIdx.x;
    int total = NATOM * KT * 32;
    if (idx >= total) return;
    int lane = idx & 31;
    int tile = idx >> 5;
    int kt = tile % KT, mt = tile / KT;
    int g = lane >> 2, t2 = (lane & 3) * 2;
    uint32_t hi[4], lo[4];
#pragma unroll
    for (int r = 0; r < 4; r++) {
        int m = mt * 16 + g + ((r & 1) << 3);
        int k = kt * 16 + t2 + ((r >> 1) << 3);
        float v0 = (m < NN) ? x[(size_t)m * IN_DIM + k] : 0.f;
        float v1 = (m < NN) ? x[(size_t)m * IN_DIM + k + 1] : 0.f;
        __nv_bfloat16 h0 = __float2bfloat16(v0);
        __nv_bfloat16 h1 = __float2bfloat16(v1);
        __nv_bfloat16 l0 = __float2bfloat16(v0 - __bfloat162float(h0));
        __nv_bfloat16 l1 = __float2bfloat16(v1 - __bfloat162float(h1));
        hi[r] = pack_bf2(h0, h1);
        lo[r] = pack_bf2(l0, l1);
    }
    ((uint4*)g_Ahi)[tile * 32 + lane] = *(uint4*)hi;
    ((uint4*)g_Alo)[tile * 32 + lane] = *(uint4*)lo;
}

__global__ void prep_w_kernel(const float* __restrict__ W, int K) {
    int KT = K / 16;
    int idx = blockIdx.x * blockDim.x + threadIdx.x;
    if (idx < 8) g_lmax[idx] = -1e30f;
    int total = HH * KT * 8 * 32;
    if (idx >= total) return;
    int lane = idx & 31;
    int tile = idx >> 5;
    int nt = tile & 7;
    int hk = tile >> 3;
    int kt = hk % KT, h = hk / KT;
    int g = lane >> 2, t2 = (lane & 3) * 2;
    uint32_t hi[2], lo[2];
#pragma unroll
    for (int r = 0; r < 2; r++) {
        int k = kt * 16 + t2 + r * 8;
        int n = h * DD + nt * 8 + g;
        float v0 = W[(size_t)k * HD + n];
        float v1 = W[(size_t)(k + 1) * HD + n];
        __nv_bfloat16 h0 = __float2bfloat16(v0);
        __nv_bfloat16 h1 = __float2bfloat16(v1);
        __nv_bfloat16 l0 = __float2bfloat16(v0 - __bfloat162float(h0));
        __nv_bfloat16 l1 = __float2bfloat16(v1 - __bfloat162float(h1));
        hi[r] = pack_bf2(h0, h1);
        lo[r] = pack_bf2(l0, l1);
    }
    ((uint2*)g_Bhi)[tile * 32 + lane] = *(uint2*)hi;
    ((uint2*)g_Blo)[tile * 32 + lane] = *(uint2*)lo;
}

// ---------------- HMMA GEMM: 2 m-atoms per warp (M=256/CTA, N=64 = 1 head) ----------------
template <int K>
__global__ void __launch_bounds__(256, 2)
hmma_gemm_kernel(const float* __restrict__ al, const float* __restrict__ arv) {
    const int KT = K / 16;
    __shared__ float al_s[64], ar_s[64];
    int tid = threadIdx.x, w = tid >> 5, lane = tid & 31;
    int h = blockIdx.x;
    int mt0 = blockIdx.y * 16 + w;
    int mt1 = mt0 + 8;
    if (mt1 >= NATOM) mt1 = mt0;   // clamp: duplicate compute, identical writes (benign)
    if (tid < 64) al_s[tid] = al[h * DD + tid];
    else if (tid < 128) ar_s[tid - 64] = arv[h * DD + tid - 64];
    __syncthreads();

    const uint4* Ah4 = (const uint4*)g_Ahi;
    const uint4* Al4 = (const uint4*)g_Alo;
    const uint2* Bh2 = (const uint2*)g_Bhi;
    const uint2* Bl2 = (const uint2*)g_Blo;

    float acc[16][4] = {};
#pragma unroll 1
    for (int kt = 0; kt < KT; kt++) {
        int tb = ((h * KT + kt) * 8) * 32 + lane;
        uint2 b_h[8], b_l[8];
#pragma unroll
        for (int nt = 0; nt < 8; nt++) {
            b_h[nt] = Bh2[tb + nt * 32];
            b_l[nt] = Bl2[tb + nt * 32];
        }
        uint4 a_h0 = Ah4[(mt0 * KT + kt) * 32 + lane];
        uint4 a_l0 = Al4[(mt0 * KT + kt) * 32 + lane];
        uint4 a_h1 = Ah4[(mt1 * KT + kt) * 32 + lane];
        uint4 a_l1 = Al4[(mt1 * KT + kt) * 32 + lane];
#pragma unroll
        for (int nt = 0; nt < 8; nt++) {
            mma_bf16(acc[nt], (const uint32_t*)&a_h0, (const uint32_t*)&b_h[nt]);
            mma_bf16(acc[8 + nt], (const uint32_t*)&a_h1, (const uint32_t*)&b_h[nt]);
            mma_bf16(acc[nt], (const uint32_t*)&a_h0, (const uint32_t*)&b_l[nt]);
            mma_bf16(acc[8 + nt], (const uint32_t*)&a_h1, (const uint32_t*)&b_l[nt]);
            mma_bf16(acc[nt], (const uint32_t*)&a_l0, (const uint32_t*)&b_h[nt]);
            mma_bf16(acc[8 + nt], (const uint32_t*)&a_l1, (const uint32_t*)&b_h[nt]);
        }
    }

    int g = lane >> 2, t2 = (lane & 3) * 2;
    half2* F = (half2*)g_feat16;
#pragma unroll
    for (int t = 0; t < 2; t++) {
        int mt = t ? mt1 : mt0;
        int row0 = mt * 16 + g, row1 = row0 + 8;
        float el0 = 0.f, el1 = 0.f, er0 = 0.f, er1 = 0.f;
#pragma unroll
        for (int nt = 0; nt < 8; nt++) {
            float* a4 = acc[t * 8 + nt];
            int cb = nt * 8 + t2;
            float a0 = al_s[cb], a1 = al_s[cb + 1];
            float r0 = ar_s[cb], r1 = ar_s[cb + 1];
            el0 += a4[0] * a0 + a4[1] * a1;
            er0 += a4[0] * r0 + a4[1] * r1;
            el1 += a4[2] * a0 + a4[3] * a1;
            er1 += a4[2] * r0 + a4[3] * r1;
            int cidx = (h * DD + cb) >> 1;
            if (row0 < NN) F[row0 * (HD / 2) + cidx] = __floats2half2_rn(a4[0], a4[1]);
            if (row1 < NN) F[row1 * (HD / 2) + cidx] = __floats2half2_rn(a4[2], a4[3]);
        }
#pragma unroll
        for (int off = 1; off <= 2; off <<= 1) {
            el0 += __shfl_xor_sync(0xffffffffu, el0, off);
            el1 += __shfl_xor_sync(0xffffffffu, el1, off);
            er0 += __shfl_xor_sync(0xffffffffu, er0, off);
            er1 += __shfl_xor_sync(0xffffffffu, er1, off);
        }
        if ((lane & 3) == 0) {
            if (row0 < NN) { g_el[row0 * HH + h] = el0; g_er[row0 * HH + h] = er0; }
            if (row1 < NN) { g_el[row1 * HH + h] = el1; g_er[row1 * HH + h] = er1; }
        }
        float ml = fmaxf(row0 < NN ? el0 : -1e30f, row1 < NN ? el1 : -1e30f);
        float mr = fmaxf(row0 < NN ? er0 : -1e30f, row1 < NN ? er1 : -1e30f);
#pragma unroll
        for (int off = 16; off; off >>= 1) {
            ml = fmaxf(ml, __shfl_xor_sync(0xffffffffu, ml, off));
            mr = fmaxf(mr, __shfl_xor_sync(0xffffffffu, mr, off));
        }
        if (lane == 0) {
            atomicMaxFloat(&g_lmax[h], ml);
            atomicMaxFloat(&g_lmax[4 + h], mr);
        }
    }
}

// ---------------- per-edge softmax weights (R7 verbatim) ----------------
__global__ void wcalc_kernel() {
    int p = blockIdx.x * blockDim.x + threadIdx.x;
    if (p >= EE) return;
    int s = g_esrc[p], d = g_edst[p];
    float4 el = *(const float4*)&g_el[s * HH];
    float4 er = *(const float4*)&g_er[d * HH];
    float M0 = fmaxf(g_lmax[0] + g_lmax[4], 0.f);
    float M1 = fmaxf(g_lmax[1] + g_lmax[5], 0.f);
    float M2 = fmaxf(g_lmax[2] + g_lmax[6], 0.f);
    float M3 = fmaxf(g_lmax[3] + g_lmax[7], 0.f);
    float e0 = el.x + er.x, e1 = el.y + er.y, e2 = el.z + er.z, e3 = el.w + er.w;
    e0 = e0 > 0.f ? e0 : 0.2f * e0;
    e1 = e1 > 0.f ? e1 : 0.2f * e1;
    e2 = e2 > 0.f ? e2 : 0.2f * e2;
    e3 = e3 > 0.f ? e3 : 0.2f * e3;
    g_w[0 * EE + p] = __expf(e0 - M0);
    g_w[1 * EE + p] = __expf(e1 - M1);
    g_w[2 * EE + p] = __expf(e2 - M2);
    g_w[3 * EE + p] = __expf(e3 - M3);
}

// ---------------- aggregation (R7 verbatim) ----------------
__global__ void __launch_bounds__(256, 6)
agg_kernel(const float* __restrict__ hin, float* __restrict__ hout,
           int residual, int activate, int write_bf16) {
    int n = blockIdx.x * 2 + (threadIdx.x >> 7);
    int h = (threadIdx.x >> 5) & 3;
    int lane = threadIdx.x & 31;
    const half2* F = (const half2*)g_feat16;

    float o0 = 0.f, o1 = 0.f;
    if (n < NN) {
        int s0 = __ldg(&g_rowptr[n]), s1 = __ldg(&g_rowptr[n + 1]);
        float a0 = 0.f, a1 = 0.f, sw = 0.f;
        for (int base = s0; base < s1; base += 32) {
            int cnt = min(32, s1 - base);
            int sidx = 0;
            float w = 0.f;
            if (lane < cnt) {
                sidx = __ldg(&g_esrc[base + lane]);
                w = __ldg(&g_w[h * EE + base + lane]);
            }
            sw += w;
#pragma unroll 8
            for (int j = 0; j < cnt; j++) {
                int sj = __shfl_sync(0xffffffffu, sidx, j);
                float wj = __shfl_sync(0xffffffffu, w, j);
                float2 vf = __half22float2(__ldg(&F[sj * (HD / 2) + h * 32 + lane]));
                a0 = fmaf(wj, vf.x, a0);
                a1 = fmaf(wj, vf.y, a1);
            }
        }
#pragma unroll
        for (int off = 16; off; off >>= 1)
            sw += __shfl_xor_sync(0xffffffffu, sw, off);
        float inv = 1.f / fmaxf(sw, 1e-9f);
        o0 = a0 * inv;
        o1 = a1 * inv;
        size_t outb = (size_t)n * HD + h * DD + 2 * lane;
        if (residual) {
            float2 r = *(const float2*)&hin[outb];
            o0 += r.x;
            o1 += r.y;
        }
        if (activate) {
            o0 = o0 > 0.f ? o0 : (__expf(o0) - 1.f);
            o1 = o1 > 0.f ? o1 : (__expf(o1) - 1.f);
        }
        *(float2*)&hout[outb] = make_float2(o0, o1);
    }
    if (write_bf16 && n < MPAD) {
        int k0 = h * DD + 2 * lane;
        size_t i0 = a_frag_idx(n, k0, HD);
        __nv_bfloat16 h0 = __float2bfloat16(o0);
        __nv_bfloat16 l0 = __float2bfloat16(o0 - __bfloat162float(h0));
        __nv_bfloat16 h1 = __float2bfloat16(o1);
        __nv_bfloat16 l1 = __float2bfloat16(o1 - __bfloat162float(h1));
        ((uint32_t*)g_Ahi)[i0 >> 1] = pack_bf2(h0, h1);
        ((uint32_t*)g_Alo)[i0 >> 1] = pack_bf2(l0, l1);
    }
}

// ---------------- readout + classifier (R7 verbatim) ----------------
__global__ void readout_kernel(const float* __restrict__ hfin, const int* __restrict__ gid) {
    int warp = threadIdx.x >> 5;
    int lane = threadIdx.x & 31;
    int base_n = (blockIdx.x * 8 + warp) * 8;
    if (base_n >= NN) return;
    float acc0 = 0.f, acc1 = 0.f;
    int cur = gid[base_n];
    int cnt = 0;
#pragma unroll
    for (int k = 0; k < 8; k++) {
        int n = base_n + k;
        if (n >= NN) break;
        int g = gid[n];
        if (g != cur) {
            atomicAdd(&g_hg[cur * DD + lane], acc0);
            atomicAdd(&g_hg[cur * DD + lane + 32], acc1);
            if (lane == 0) atomicAdd(&g_cnt[cur], (float)cnt);
            cur = g; acc0 = acc1 = 0.f; cnt = 0;
        }
        const float* f = &hfin[(size_t)n * HD];
        acc0 += 0.25f * (f[lane] + f[DD + lane] + f[2 * DD + lane] + f[3 * DD + lane]);
        acc1 += 0.25f * (f[lane + 32] + f[DD + lane + 32] + f[2 * DD + lane + 32] + f[3 * DD + lane + 32]);
        cnt++;
    }
    atomicAdd(&g_hg[cur * DD + lane], acc0);
    atomicAdd(&g_hg[cur * DD + lane + 32], acc1);
    if (lane == 0) atomicAdd(&g_cnt[cur], (float)cnt);
}

__global__ void classifier_kernel(const float* __restrict__ Wc, const float* __restrict__ bc,
                                  float* __restrict__ out) {
    int t = threadIdx.x;
    if (t >= GGR * CC) return;
    int g = t / CC, c = t % CC;
    float s = 0.f;
#pragma unroll
    for (int d = 0; d < DD; d++) s += g_hg[g * DD + d] * Wc[d * CC + c];
    out[t] = s / fmaxf(g_cnt[g], 1.0f) + bc[c];
}

// ---------------- host ----------------
extern "C" void kernel_launch(void* const* d_in, const int* in_sizes, int n_in,
                              void* d_out, int out_size) {
    const float* x   = (const float*)d_in[0];
    const int*   src = (const int*)d_in[1];
    const int*   dst = (const int*)d_in[2];
    const int*   gid = (const int*)d_in[3];
    const float* W0  = (const float*)d_in[4];
    const float* al0 = (const float*)d_in[5];
    const float* ar0 = (const float*)d_in[6];
    const float* W1  = (const float*)d_in[7];
    const float* al1 = (const float*)d_in[8];
    const float* ar1 = (const float*)d_in[9];
    const float* W2  = (const float*)d_in[10];
    const float* al2 = (const float*)d_in[11];
    const float* ar2 = (const float*)d_in[12];
    const float* Wc  = (const float*)d_in[13];
    const float* bc  = (const float*)d_in[14];
    float* out = (float*)d_out;

    void *p_h1, *p_h2;
    cudaGetSymbolAddress(&p_h1, g_h1);
    cudaGetSymbolAddress(&p_h2, g_h2);
    float* f_h1 = (float*)p_h1;
    float* f_h2 = (float*)p_h2;

    dim3 mgrid(HH, (NATOM + 15) / 16);   // 1 head x 256 rows per CTA

    prep_x_kernel<<<(NATOM * (IN_DIM / 16) * 32 + 255) / 256, 256>>>(x);           // 0
    prep_w_kernel<<<(HH * (IN_DIM / 16) * 8 * 32 + 255) / 256, 256>>>(W0, IN_DIM); // 1
    zero_kernel<<<(NN + 255) / 256, 256>>>();                                       // 2
    hmma_gemm_kernel<IN_DIM><<<mgrid, 256>>>(al0, ar0);                             // 3 <- ncu capture
    // CSR build
    hist_kernel<<<(EE + 255) / 256, 256>>>(dst);
    scan1_kernel<<<SCAN_B, 1024>>>();
    scan2_kernel<<<1, 64>>>();
    scan3_kernel<<<SCAN_B, 1024>>>();
    scatter_kernel<<<(EE + 255) / 256, 256>>>(dst, src);

    // ---- layer 0 tail ----
    wcalc_kernel<<<(EE + 255) / 256, 256>>>();
    agg_kernel<<<MPAD / 2, 256>>>(nullptr, f_h1, 0, 1, 1);

    // ---- layer 1 ----
    prep_w_kernel<<<(HH * (HD / 16) * 8 * 32 + 255) / 256, 256>>>(W1, HD);
    hmma_gemm_kernel<HD><<<mgrid, 256>>>(al1, ar1);
    wcalc_kernel<<<(EE + 255) / 256, 256>>>();
    agg_kernel<<<MPAD / 2, 256>>>(f_h1, f_h2, 1, 1, 1);

    // ---- layer 2 ----
    prep_w_kernel<<<(HH * (HD / 16) * 8 * 32 + 255) / 256, 256>>>(W2, HD);
    hmma_gemm_kernel<HD><<<mgrid, 256>>>(al2, ar2);
    wcalc_kernel<<<(EE + 255) / 256, 256>>>();
    agg_kernel<<<(NN + 1) / 2, 256>>>(f_h2, f_h1, 1, 0, 0);

    // ---- readout + classifier ----
    readout_kernel<<<(NN + 63) / 64, 256>>>(f_h1, gid);
    classifier_kernel<<<1, GGR * CC>>>(Wc, bc, out);
}

// round 12
// speedup vs baseline: 1.1762x; 1.0120x over previous
#include <cuda_runtime.h>
#include <cuda_bf16.h>
#include <cuda_fp16.h>
#include <cstdint>

#define NN 40000
#define EE 400000
#define GGR 64
#define IN_DIM 128
#define DD 64
#define HH 4
#define CC 10
#define HD 256      // H*D
#define MTILES 313  // ceil(40000/128)
#define MPAD (MTILES * 128)
#define NATOM (MPAD / 16)
#define SCAN_B 40

// ---------------- static device scratch ----------------
__device__ __half g_feat16[NN * HD];
__device__ float g_h1[NN * HD];
__device__ float g_h2[NN * HD];
__device__ float g_el[NN * HH];
__device__ float g_er[NN * HH];
__device__ float g_lmax[8];
__device__ float g_w[HH * EE];
__device__ int   g_counts[NN];
__device__ int   g_rowptr[NN + 1];
__device__ int   g_cursor[NN];
__device__ int   g_bsum[SCAN_B];
__device__ int   g_esrc[EE];
__device__ int   g_edst[EE];
__device__ float g_hg[GGR * DD];
__device__ float g_cnt[GGR];
__device__ __nv_bfloat16 g_Ahi[MPAD * HD];
__device__ __nv_bfloat16 g_Alo[MPAD * HD];
__device__ __nv_bfloat16 g_Bhi[HH * DD * HD];
__device__ __nv_bfloat16 g_Blo[HH * DD * HD];

__device__ __forceinline__ void atomicMaxFloat(float* addr, float value) {
    if (value >= 0.f)
        atomicMax((int*)addr, __float_as_int(value));
    else
        atomicMin((unsigned int*)addr, __float_as_uint(value));
}

__device__ __forceinline__ uint32_t pack_bf2(__nv_bfloat16 lo, __nv_bfloat16 hi) {
    return (uint32_t)__bfloat16_as_ushort(lo) | ((uint32_t)__bfloat16_as_ushort(hi) << 16);
}

__device__ __forceinline__ size_t a_frag_idx(int m, int k, int K) {
    int mt = m >> 4, rr = m & 15;
    int kt = k >> 4, cin = k & 15;
    int g = rr & 7;
    int r = (rr >> 3) | ((cin >> 3) << 1);
    int lane = g * 4 + ((cin & 6) >> 1);
    int tile = mt * (K >> 4) + kt;
    return ((size_t)(tile * 32 + lane) * 4 + r) * 2 + (cin & 1);
}

__device__ __forceinline__ void mma_bf16(float* c, const uint32_t* a, const uint32_t* b) {
    asm volatile(
        "mma.sync.aligned.m16n8k16.row.col.f32.bf16.bf16.f32 "
        "{%0,%1,%2,%3}, {%4,%5,%6,%7}, {%8,%9}, {%0,%1,%2,%3};"
        : "+f"(c[0]), "+f"(c[1]), "+f"(c[2]), "+f"(c[3])
        : "r"(a[0]), "r"(a[1]), "r"(a[2]), "r"(a[3]), "r"(b[0]), "r"(b[1]));
}

__device__ __forceinline__ void cp_async16(uint32_t smem_addr, const void* gptr) {
    asm volatile("cp.async.cg.shared.global [%0], [%1], 16;"
                 :: "r"(smem_addr), "l"(gptr) : "memory");
}

// ---------------- init + CSR build (R7 verbatim) ----------------
__global__ void zero_kernel() {
    int t = blockIdx.x * blockDim.x + threadIdx.x;
    if (t < NN) { g_counts[t] = 0; g_cursor[t] = 0; }
    if (t < GGR * DD) g_hg[t] = 0.f;
    if (t < GGR) g_cnt[t] = 0.f;
}

__global__ void hist_kernel(const int* __restrict__ dst) {
    int t = blockIdx.x * blockDim.x + threadIdx.x;
    if (t < EE) atomicAdd(&g_counts[dst[t]], 1);
}

__global__ void scan1_kernel() {
    __shared__ int sh[1024];
    int t = threadIdx.x;
    int idx = blockIdx.x * 1024 + t;
    int v = (idx < NN) ? g_counts[idx] : 0;
    sh[t] = v;
    __syncthreads();
    for (int off = 512; off; off >>= 1) {
        if (t < off) sh[t] += sh[t + off];
        __syncthreads();
    }
    if (t == 0) g_bsum[blockIdx.x] = sh[0];
}

__global__ void scan2_kernel() {
    int t = threadIdx.x;
    __shared__ int sh[64];
    int v = (t < SCAN_B) ? g_bsum[t] : 0;
    sh[t] = v;
    __syncthreads();
    for (int off = 1; off < 64; off <<= 1) {
        int add = (t >= off) ? sh[t - off] : 0;
        __syncthreads();
        sh[t] += add;
        __syncthreads();
    }
    if (t < SCAN_B) g_bsum[t] = sh[t] - v;
}

__global__ void scan3_kernel() {
    __shared__ int sh[1024];
    int t = threadIdx.x;
    int idx = blockIdx.x * 1024 + t;
    int v = (idx < NN) ? g_counts[idx] : 0;
    sh[t] = v;
    __syncthreads();
    for (int off = 1; off < 1024; off <<= 1) {
        int add = (t >= off) ? sh[t - off] : 0;
        __syncthreads();
        sh[t] += add;
        __syncthreads();
    }
    int off = g_bsum[blockIdx.x];
    if (idx < NN) g_rowptr[idx + 1] = off + sh[t];
    if (idx == 0) g_rowptr[0] = 0;
}

__global__ void scatter_kernel(const int* __restrict__ dst, const int* __restrict__ src) {
    int t = blockIdx.x * blockDim.x + threadIdx.x;
    if (t < EE) {
        int d = dst[t];
        int pos = g_rowptr[d] + atomicAdd(&g_cursor[d], 1);
        g_esrc[pos] = src[t];
        g_edst[pos] = d;
    }
}

// ---------------- prep kernels (R7 verbatim) ----------------
__global__ void prep_x_kernel(const float* __restrict__ x) {
    const int KT = IN_DIM / 16;
    int idx = blockIdx.x * blockDim.x + threadIdx.x;
    int total = NATOM * KT * 32;
    if (idx >= total) return;
    int lane = idx & 31;
    int tile = idx >> 5;
    int kt = tile % KT, mt = tile / KT;
    int g = lane >> 2, t2 = (lane & 3) * 2;
    uint32_t hi[4], lo[4];
#pragma unroll
    for (int r = 0; r < 4; r++) {
        int m = mt * 16 + g + ((r & 1) << 3);
        int k = kt * 16 + t2 + ((r >> 1) << 3);
        float v0 = (m < NN) ? x[(size_t)m * IN_DIM + k] : 0.f;
        float v1 = (m < NN) ? x[(size_t)m * IN_DIM + k + 1] : 0.f;
        __nv_bfloat16 h0 = __float2bfloat16(v0);
        __nv_bfloat16 h1 = __float2bfloat16(v1);
        __nv_bfloat16 l0 = __float2bfloat16(v0 - __bfloat162float(h0));
        __nv_bfloat16 l1 = __float2bfloat16(v1 - __bfloat162float(h1));
        hi[r] = pack_bf2(h0, h1);
        lo[r] = pack_bf2(l0, l1);
    }
    ((uint4*)g_Ahi)[tile * 32 + lane] = *(uint4*)hi;
    ((uint4*)g_Alo)[tile * 32 + lane] = *(uint4*)lo;
}

__global__ void prep_w_kernel(const float* __restrict__ W, int K) {
    int KT = K / 16;
    int idx = blockIdx.x * blockDim.x + threadIdx.x;
    if (idx < 8) g_lmax[idx] = -1e30f;
    int total = HH * KT * 8 * 32;
    if (idx >= total) return;
    int lane = idx & 31;
    int tile = idx >> 5;
    int nt = tile & 7;
    int hk = tile >> 3;
    int kt = hk % KT, h = hk / KT;
    int g = lane >> 2, t2 = (lane & 3) * 2;
    uint32_t hi[2], lo[2];
#pragma unroll
    for (int r = 0; r < 2; r++) {
        int k = kt * 16 + t2 + r * 8;
        int n = h * DD + nt * 8 + g;
        float v0 = W[(size_t)k * HD + n];
        float v1 = W[(size_t)(k + 1) * HD + n];
        __nv_bfloat16 h0 = __float2bfloat16(v0);
        __nv_bfloat16 h1 = __float2bfloat16(v1);
        __nv_bfloat16 l0 = __float2bfloat16(v0 - __bfloat162float(h0));
        __nv_bfloat16 l1 = __float2bfloat16(v1 - __bfloat162float(h1));
        hi[r] = pack_bf2(h0, h1);
        lo[r] = pack_bf2(l0, l1);
    }
    ((uint2*)g_Bhi)[tile * 32 + lane] = *(uint2*)hi;
    ((uint2*)g_Blo)[tile * 32 + lane] = *(uint2*)lo;
}

// ---------------- HMMA GEMM: cp.async-pipelined A stream (depth 4) ----------------
// grid (HH, MTILES), 256 threads; warp w owns m-atom blockIdx.y*8+w, N=64 (1 head).
// Each thread prefetches ITS OWN A fragments 3 stages ahead -> no syncthreads needed.
template <int K>
__global__ void __launch_bounds__(256, 2)
hmma_gemm_kernel(const float* __restrict__ al, const float* __restrict__ arv) {
    const int KT = K / 16;
    const int DEPTH = 4;
    __shared__ uint4 sA[DEPTH][2][8][32];   // 32 KB: [stage][hi/lo][warp][lane]
    __shared__ float al_s[64], ar_s[64];
    int tid = threadIdx.x, w = tid >> 5, lane = tid & 31;
    int h = blockIdx.x;
    int mt = blockIdx.y * 8 + w;
    if (tid < 64) al_s[tid] = al[h * DD + tid];
    else if (tid < 128) ar_s[tid - 64] = arv[h * DD + tid - 64];
    __syncthreads();   // al_s/ar_s only (A slots are thread-private)

    const uint4* Ah4 = (const uint4*)g_Ahi;
    const uint4* Al4 = (const uint4*)g_Alo;
    const uint2* Bh2 = (const uint2*)g_Bhi;
    const uint2* Bl2 = (const uint2*)g_Blo;

    uint32_t s_hi = (uint32_t)__cvta_generic_to_shared(&sA[0][0][w][lane]);
    uint32_t s_lo = (uint32_t)__cvta_generic_to_shared(&sA[0][1][w][lane]);
    const uint32_t STG = 2 * 8 * 32 * 16;   // stage stride bytes = 8192
    size_t gbase = (size_t)(mt * KT) * 32 + lane;

    // prologue: stages 0..2
#pragma unroll
    for (int s = 0; s < DEPTH - 1; s++) {
        if (s < KT) {
            cp_async16(s_hi + s * STG, Ah4 + gbase + s * 32);
            cp_async16(s_lo + s * STG, Al4 + gbase + s * 32);
        }
        asm volatile("cp.async.commit_group;" ::: "memory");
    }

    float acc[8][4] = {};
#pragma unroll 1
    for (int kt = 0; kt < KT; kt++) {
        int pf = kt + DEPTH - 1;
        if (pf < KT) {
            uint32_t st = (pf & (DEPTH - 1)) * STG;
            cp_async16(s_hi + st, Ah4 + gbase + pf * 32);
            cp_async16(s_lo + st, Al4 + gbase + pf * 32);
        }
        asm volatile("cp.async.commit_group;" ::: "memory");
        asm volatile("cp.async.wait_group 3;" ::: "memory");

        uint4 a_h = sA[kt & (DEPTH - 1)][0][w][lane];
        uint4 a_l = sA[kt & (DEPTH - 1)][1][w][lane];
        int tb = ((h * KT + kt) * 8) * 32 + lane;
#pragma unroll
        for (int nt = 0; nt < 8; nt++) {
            uint2 b_h = __ldg(&Bh2[tb + nt * 32]);
            uint2 b_l = __ldg(&Bl2[tb + nt * 32]);
            mma_bf16(acc[nt], (const uint32_t*)&a_h, (const uint32_t*)&b_h);
            mma_bf16(acc[nt], (const uint32_t*)&a_h, (const uint32_t*)&b_l);
            mma_bf16(acc[nt], (const uint32_t*)&a_l, (const uint32_t*)&b_h);
        }
    }

    int g = lane >> 2, t2 = (lane & 3) * 2;
    int row0 = mt * 16 + g, row1 = row0 + 8;
    half2* F = (half2*)g_feat16;
    float el0 = 0.f, el1 = 0.f, er0 = 0.f, er1 = 0.f;
#pragma unroll
    for (int nt = 0; nt < 8; nt++) {
        int cb = nt * 8 + t2;
        float a0 = al_s[cb], a1 = al_s[cb + 1];
        float r0 = ar_s[cb], r1 = ar_s[cb + 1];
        el0 += acc[nt][0] * a0 + acc[nt][1] * a1;
        er0 += acc[nt][0] * r0 + acc[nt][1] * r1;
        el1 += acc[nt][2] * a0 + acc[nt][3] * a1;
        er1 += acc[nt][2] * r0 + acc[nt][3] * r1;
        int cidx = (h * DD + cb) >> 1;
        if (row0 < NN) F[row0 * (HD / 2) + cidx] = __floats2half2_rn(acc[nt][0], acc[nt][1]);
        if (row1 < NN) F[row1 * (HD / 2) + cidx] = __floats2half2_rn(acc[nt][2], acc[nt][3]);
    }
#pragma unroll
    for (int off = 1; off <= 2; off <<= 1) {
        el0 += __shfl_xor_sync(0xffffffffu, el0, off);
        el1 += __shfl_xor_sync(0xffffffffu, el1, off);
        er0 += __shfl_xor_sync(0xffffffffu, er0, off);
        er1 += __shfl_xor_sync(0xffffffffu, er1, off);
    }
    if ((lane & 3) == 0) {
        if (row0 < NN) { g_el[row0 * HH + h] = el0; g_er[row0 * HH + h] = er0; }
        if (row1 < NN) { g_el[row1 * HH + h] = el1; g_er[row1 * HH + h] = er1; }
    }
    float ml = fmaxf(row0 < NN ? el0 : -1e30f, row1 < NN ? el1 : -1e30f);
    float mr = fmaxf(row0 < NN ? er0 : -1e30f, row1 < NN ? er1 : -1e30f);
#pragma unroll
    for (int off = 16; off; off >>= 1) {
        ml = fmaxf(ml, __shfl_xor_sync(0xffffffffu, ml, off));
        mr = fmaxf(mr, __shfl_xor_sync(0xffffffffu, mr, off));
    }
    if (lane == 0) {
        atomicMaxFloat(&g_lmax[h], ml);
        atomicMaxFloat(&g_lmax[4 + h], mr);
    }
}

// ---------------- per-edge softmax weights (R7 verbatim) ----------------
__global__ void wcalc_kernel() {
    int p = blockIdx.x * blockDim.x + threadIdx.x;
    if (p >= EE) return;
    int s = g_esrc[p], d = g_edst[p];
    float4 el = *(const float4*)&g_el[s * HH];
    float4 er = *(const float4*)&g_er[d * HH];
    float M0 = fmaxf(g_lmax[0] + g_lmax[4], 0.f);
    float M1 = fmaxf(g_lmax[1] + g_lmax[5], 0.f);
    float M2 = fmaxf(g_lmax[2] + g_lmax[6], 0.f);
    float M3 = fmaxf(g_lmax[3] + g_lmax[7], 0.f);
    float e0 = el.x + er.x, e1 = el.y + er.y, e2 = el.z + er.z, e3 = el.w + er.w;
    e0 = e0 > 0.f ? e0 : 0.2f * e0;
    e1 = e1 > 0.f ? e1 : 0.2f * e1;
    e2 = e2 > 0.f ? e2 : 0.2f * e2;
    e3 = e3 > 0.f ? e3 : 0.2f * e3;
    g_w[0 * EE + p] = __expf(e0 - M0);
    g_w[1 * EE + p] = __expf(e1 - M1);
    g_w[2 * EE + p] = __expf(e2 - M2);
    g_w[3 * EE + p] = __expf(e3 - M3);
}

// ---------------- aggregation (R7 verbatim) ----------------
__global__ void __launch_bounds__(256, 6)
agg_kernel(const float* __restrict__ hin, float* __restrict__ hout,
           int residual, int activate, int write_bf16) {
    int n = blockIdx.x * 2 + (threadIdx.x >> 7);
    int h = (threadIdx.x >> 5) & 3;
    int lane = threadIdx.x & 31;
    const half2* F = (const half2*)g_feat16;

    float o0 = 0.f, o1 = 0.f;
    if (n < NN) {
        int s0 = __ldg(&g_rowptr[n]), s1 = __ldg(&g_rowptr[n + 1]);
        float a0 = 0.f, a1 = 0.f, sw = 0.f;
        for (int base = s0; base < s1; base += 32) {
            int cnt = min(32, s1 - base);
            int sidx = 0;
            float w = 0.f;
            if (lane < cnt) {
                sidx = __ldg(&g_esrc[base + lane]);
                w = __ldg(&g_w[h * EE + base + lane]);
            }
            sw += w;
#pragma unroll 8
            for (int j = 0; j < cnt; j++) {
                int sj = __shfl_sync(0xffffffffu, sidx, j);
                float wj = __shfl_sync(0xffffffffu, w, j);
                float2 vf = __half22float2(__ldg(&F[sj * (HD / 2) + h * 32 + lane]));
                a0 = fmaf(wj, vf.x, a0);
                a1 = fmaf(wj, vf.y, a1);
            }
        }
#pragma unroll
        for (int off = 16; off; off >>= 1)
            sw += __shfl_xor_sync(0xffffffffu, sw, off);
        float inv = 1.f / fmaxf(sw, 1e-9f);
        o0 = a0 * inv;
        o1 = a1 * inv;
        size_t outb = (size_t)n * HD + h * DD + 2 * lane;
        if (residual) {
            float2 r = *(const float2*)&hin[outb];
            o0 += r.x;
            o1 += r.y;
        }
        if (activate) {
            o0 = o0 > 0.f ? o0 : (__expf(o0) - 1.f);
            o1 = o1 > 0.f ? o1 : (__expf(o1) - 1.f);
        }
        *(float2*)&hout[outb] = make_float2(o0, o1);
    }
    if (write_bf16 && n < MPAD) {
        int k0 = h * DD + 2 * lane;
        size_t i0 = a_frag_idx(n, k0, HD);
        __nv_bfloat16 h0 = __float2bfloat16(o0);
        __nv_bfloat16 l0 = __float2bfloat16(o0 - __bfloat162float(h0));
        __nv_bfloat16 h1 = __float2bfloat16(o1);
        __nv_bfloat16 l1 = __float2bfloat16(o1 - __bfloat162float(h1));
        ((uint32_t*)g_Ahi)[i0 >> 1] = pack_bf2(h0, h1);
        ((uint32_t*)g_Alo)[i0 >> 1] = pack_bf2(l0, l1);
    }
}

// ---------------- readout + classifier (R7 verbatim) ----------------
__global__ void readout_kernel(const float* __restrict__ hfin, const int* __restrict__ gid) {
    int warp = threadIdx.x >> 5;
    int lane = threadIdx.x & 31;
    int base_n = (blockIdx.x * 8 + warp) * 8;
    if (base_n >= NN) return;
    float acc0 = 0.f, acc1 = 0.f;
    int cur = gid[base_n];
    int cnt = 0;
#pragma unroll
    for (int k = 0; k < 8; k++) {
        int n = base_n + k;
        if (n >= NN) break;
        int g = gid[n];
        if (g != cur) {
            atomicAdd(&g_hg[cur * DD + lane], acc0);
            atomicAdd(&g_hg[cur * DD + lane + 32], acc1);
            if (lane == 0) atomicAdd(&g_cnt[cur], (float)cnt);
            cur = g; acc0 = acc1 = 0.f; cnt = 0;
        }
        const float* f = &hfin[(size_t)n * HD];
        acc0 += 0.25f * (f[lane] + f[DD + lane] + f[2 * DD + lane] + f[3 * DD + lane]);
        acc1 += 0.25f * (f[lane + 32] + f[DD + lane + 32] + f[2 * DD + lane + 32] + f[3 * DD + lane + 32]);
        cnt++;
    }
    atomicAdd(&g_hg[cur * DD + lane], acc0);
    atomicAdd(&g_hg[cur * DD + lane + 32], acc1);
    if (lane == 0) atomicAdd(&g_cnt[cur], (float)cnt);
}

__global__ void classifier_kernel(const float* __restrict__ Wc, const float* __restrict__ bc,
                                  float* __restrict__ out) {
    int t = threadIdx.x;
    if (t >= GGR * CC) return;
    int g = t / CC, c = t % CC;
    float s = 0.f;
#pragma unroll
    for (int d = 0; d < DD; d++) s += g_hg[g * DD + d] * Wc[d * CC + c];
    out[t] = s / fmaxf(g_cnt[g], 1.0f) + bc[c];
}

// ---------------- host ----------------
extern "C" void kernel_launch(void* const* d_in, const int* in_sizes, int n_in,
                              void* d_out, int out_size) {
    const float* x   = (const float*)d_in[0];
    const int*   src = (const int*)d_in[1];
    const int*   dst = (const int*)d_in[2];
    const int*   gid = (const int*)d_in[3];
    const float* W0  = (const float*)d_in[4];
    const float* al0 = (const float*)d_in[5];
    const float* ar0 = (const float*)d_in[6];
    const float* W1  = (const float*)d_in[7];
    const float* al1 = (const float*)d_in[8];
    const float* ar1 = (const float*)d_in[9];
    const float* W2  = (const float*)d_in[10];
    const float* al2 = (const float*)d_in[11];
    const float* ar2 = (const float*)d_in[12];
    const float* Wc  = (const float*)d_in[13];
    const float* bc  = (const float*)d_in[14];
    float* out = (float*)d_out;

    void *p_h1, *p_h2;
    cudaGetSymbolAddress(&p_h1, g_h1);
    cudaGetSymbolAddress(&p_h2, g_h2);
    float* f_h1 = (float*)p_h1;
    float* f_h2 = (float*)p_h2;

    dim3 mgrid(HH, MTILES);   // warp w owns m-atom by*8+w

    prep_x_kernel<<<(NATOM * (IN_DIM / 16) * 32 + 255) / 256, 256>>>(x);           // 0
    prep_w_kernel<<<(HH * (IN_DIM / 16) * 8 * 32 + 255) / 256, 256>>>(W0, IN_DIM); // 1
    zero_kernel<<<(NN + 255) / 256, 256>>>();                                       // 2
    hmma_gemm_kernel<IN_DIM><<<mgrid, 256>>>(al0, ar0);                             // 3 <- ncu capture
    // CSR build
    hist_kernel<<<(EE + 255) / 256, 256>>>(dst);
    scan1_kernel<<<SCAN_B, 1024>>>();
    scan2_kernel<<<1, 64>>>();
    scan3_kernel<<<SCAN_B, 1024>>>();
    scatter_kernel<<<(EE + 255) / 256, 256>>>(dst, src);

    // ---- layer 0 tail ----
    wcalc_kernel<<<(EE + 255) / 256, 256>>>();
    agg_kernel<<<MPAD / 2, 256>>>(nullptr, f_h1, 0, 1, 1);

    // ---- layer 1 ----
    prep_w_kernel<<<(HH * (HD / 16) * 8 * 32 + 255) / 256, 256>>>(W1, HD);
    hmma_gemm_kernel<HD><<<mgrid, 256>>>(al1, ar1);
    wcalc_kernel<<<(EE + 255) / 256, 256>>>();
    agg_kernel<<<MPAD / 2, 256>>>(f_h1, f_h2, 1, 1, 1);

    // ---- layer 2 ----
    prep_w_kernel<<<(HH * (HD / 16) * 8 * 32 + 255) / 256, 256>>>(W2, HD);
    hmma_gemm_kernel<HD><<<mgrid, 256>>>(al2, ar2);
    wcalc_kernel<<<(EE + 255) / 256, 256>>>();
    agg_kernel<<<(NN + 1) / 2, 256>>>(f_h2, f_h1, 1, 0, 0);

    // ---- readout + classifier ----
    readout_kernel<<<(NN + 63) / 64, 256>>>(f_h1, gid);
    classifier_kernel<<<1, GGR * CC>>>(Wc, bc, out);
}